// round 10
// baseline (speedup 1.0000x reference)
#include <cuda_runtime.h>
#include <cstdint>
#include <math.h>

#define BB    512
#define STATE 256
#define DES   128
#define H     512
#define SPLITS 18
#define STG   8     // B ring stages (deep pipeline)
#define SBW   140   // sB row stride (words) -> conflict-free B frag LDS
#define AW    12    // sA row stride (words, 48B) -> conflict-free STS.128 + ldmatrix

#define SA_WORDS (2 * 128 * AW)                       // 3072
#define SMEM_BYTES ((SA_WORDS + STG * 16 * SBW) * 4)  // 83968 (2 CTAs/SM: 164KB < 228KB)

__device__ float g_buf0[BB * H];
__device__ float g_buf1[BB * H];
__device__ float g_part[SPLITS][BB][H];

__device__ __forceinline__ uint32_t pack_h2(float lo, float hi) {
    uint32_t r;
    asm("cvt.rn.f16x2.f32 %0, %1, %2;" : "=r"(r) : "f"(hi), "f"(lo));
    return r;
}
__device__ __forceinline__ void mma16816(float* c,
                                         uint32_t a0, uint32_t a1, uint32_t a2, uint32_t a3,
                                         uint32_t b0, uint32_t b1) {
    asm volatile("mma.sync.aligned.m16n8k16.row.col.f32.f16.f16.f32 "
                 "{%0,%1,%2,%3}, {%4,%5,%6,%7}, {%8,%9}, {%0,%1,%2,%3};"
                 : "+f"(c[0]), "+f"(c[1]), "+f"(c[2]), "+f"(c[3])
                 : "r"(a0), "r"(a1), "r"(a2), "r"(a3), "r"(b0), "r"(b1));
}
__device__ __forceinline__ uint32_t smem_u32(const void* p) {
    uint32_t a;
    asm("{ .reg .u64 t; cvta.to.shared.u64 t, %1; cvt.u32.u64 %0, t; }" : "=r"(a) : "l"(p));
    return a;
}
__device__ __forceinline__ void cp16(uint32_t dst, const float* src) {
    asm volatile("cp.async.cg.shared.global [%0], [%1], 16;" :: "r"(dst), "l"(src));
}
__device__ __forceinline__ void ldsm4(uint32_t& a0, uint32_t& a1, uint32_t& a2, uint32_t& a3,
                                      uint32_t addr) {
    asm volatile("ldmatrix.sync.aligned.m8n8.x4.shared.b16 {%0,%1,%2,%3}, [%4];"
                 : "=r"(a0), "=r"(a1), "=r"(a2), "=r"(a3) : "r"(addr));
}
__device__ __forceinline__ void sts128(uint32_t a, uint32_t x, uint32_t y, uint32_t z, uint32_t w) {
    asm volatile("st.shared.v4.b32 [%0], {%1,%2,%3,%4};" :: "r"(a), "r"(x), "r"(y), "r"(z), "r"(w) : "memory");
}
#define CP_COMMIT() asm volatile("cp.async.commit_group;" ::: "memory")
#define CP_WAIT6()  asm volatile("cp.async.wait_group 6;" ::: "memory")

// ---------------------------------------------------------------------------
__global__ void embed_kernel(const float* __restrict__ state,
                             const float* __restrict__ ew,
                             const float* __restrict__ eb) {
    int idx = blockIdx.x * blockDim.x + threadIdx.x;
    int b = idx >> 9;
    int j = idx & 511;
    float s = eb[j];
    const float* sp = state + b * STATE;
#pragma unroll 8
    for (int k = 0; k < STATE; k++)
        s = fmaf(sp[k], ew[k * H + j], s);
    g_buf0[idx] = tanhf(s);
}

// ---------------------------------------------------------------------------
// fp16 m16n8k16 split-K GEMM. 8-stage cp.async B ring (prefetch depth 7),
// ldmatrix A, kb-outer loop, 2 CTAs/SM.
//   virtual A[b, d*512+h] = cmd[b,d] * in[b,h]   (chunk d=128 -> hw_b, scale 1)
// ---------------------------------------------------------------------------
__global__ void __launch_bounds__(256, 2)
gemm_fp16(int layer, const float* __restrict__ cmd,
          const float* __restrict__ hwW, const float* __restrict__ hwb)
{
    extern __shared__ __align__(16) uint32_t smw[];
    float* sB = (float*)(smw + SA_WORDS);

    const int t    = threadIdx.x;
    const int lane = t & 31;
    const int w    = t >> 5;
    const int wm   = w & 1;
    const int wn   = w >> 1;
    const int q    = lane & 3;
    const int r4   = lane >> 2;

    const int n0 = blockIdx.x * 128;
    const int m0 = blockIdx.y * 128;
    const int sp = blockIdx.z;
    const int c0  = sp * 7 + (sp < 3 ? sp : 3);
    const int cnt = 7 + (sp < 3 ? 1 : 0);

    const float* __restrict__ inbuf = layer ? g_buf1 : g_buf0;

    // roles
    const int am = t & 127;
    const int kh = t >> 7;
    const float* inrow = inbuf + (size_t)(m0 + am) * H + kh * 8;

    const int brow = t >> 5;
    const int bcol4 = (t & 31) * 4;
    const uint32_t sA_u32 = smem_u32(smw);
    const uint32_t sB_u32 = smem_u32(sB);
    const uint32_t bdst1 = sB_u32 + (uint32_t)(brow * SBW + bcol4) * 4;
    const uint32_t bdst2 = bdst1 + 8 * SBW * 4;

    const uint32_t a_sts = sA_u32 + (uint32_t)(am * AW + kh * 4) * 4;
    const uint32_t a_ldm = sA_u32 + (uint32_t)((wm * 64 + (lane & 15)) * AW) * 4 + (lane >> 4) * 16;

    float sc[8];
#pragma unroll
    for (int i = 0; i < 8; i++) {
        int d = c0 + i;
        sc[i] = (i < cnt) ? ((d < DES) ? cmd[(m0 + am) * DES + d] : 1.0f) : 0.0f;
    }

    float acc[4][4][4];
#pragma unroll
    for (int i = 0; i < 4; i++)
#pragma unroll
        for (int j = 0; j < 4; j++)
#pragma unroll
            for (int k = 0; k < 4; k++) acc[i][j][k] = 0.0f;

    auto issueB = [&](int kbj, int cij, int slot) {
        int d = c0 + cij;
        const float* bb = ((d < DES) ? (hwW + (size_t)d * (H * H)) : hwb)
                          + ((size_t)kbj << 4) * H + n0;
        uint32_t so = (uint32_t)slot * (16 * SBW * 4);
        cp16(bdst1 + so, bb + brow * H + bcol4);
        cp16(bdst2 + so, bb + (brow + 8) * H + bcol4);
        CP_COMMIT();
    };

    // prologue: 7 stages in flight (iters 0..6 are kb=0, ci=0..6 since cnt>=7)
#pragma unroll
    for (int i = 0; i < 7; i++) issueB(0, i, i);
    int kb_is = 0, ci_is = 7;            // coords of iter 7
    if (ci_is >= cnt) { ci_is -= cnt; kb_is = 1; }

    float4 av0 = *(const float4*)(inrow);
    float4 av1 = *(const float4*)(inrow + 4);
    float4 nv0 = av0, nv1 = av1;

    int it = 0;
    for (int kb = 0; kb < 32; kb++) {
        for (int ci = 0; ci < cnt; ci++, it++) {
            const int buf = it & 1;
            const uint32_t bufoff = (uint32_t)buf * (128 * AW * 4);

            // stage A (scaled fp16, m-major row) — one STS.128
            {
                float s = sc[ci];
                sts128(a_sts + bufoff,
                       pack_h2(av0.x * s, av0.y * s), pack_h2(av0.z * s, av0.w * s),
                       pack_h2(av1.x * s, av1.y * s), pack_h2(av1.z * s, av1.w * s));
            }
            // prefetch next k-band of A (once per kb)
            if (ci == 0) {
                int kn = (kb < 31) ? kb + 1 : 31;
                nv0 = *(const float4*)(inrow + kn * 16);
                nv1 = *(const float4*)(inrow + kn * 16 + 4);
            }

            CP_WAIT6();
            __syncthreads();

            // keep ring full: issue iter it+7 (slot == (it-1)%STG, safe post-barrier)
            issueB(kb_is, ci_is, (it + 7) % STG);
            if (++ci_is == cnt) {
                ci_is = 0;
                if (++kb_is == 32) { kb_is = 31; ci_is = cnt - 1; }
            }

            // B fragments (fp32 -> f16x2)
            const float* sb = sB + (it % STG) * (16 * SBW);
            uint32_t bf[4][2];
#pragma unroll
            for (int ni = 0; ni < 4; ni++) {
                int col = wn * 32 + ni * 8 + r4;
                float b0 = sb[(2 * q) * SBW + col];
                float b1 = sb[(2 * q + 1) * SBW + col];
                float b2 = sb[(2 * q + 8) * SBW + col];
                float b3 = sb[(2 * q + 9) * SBW + col];
                bf[ni][0] = pack_h2(b0, b1);
                bf[ni][1] = pack_h2(b2, b3);
            }
            // A fragments via ldmatrix + MMAs
#pragma unroll
            for (int mi = 0; mi < 4; mi++) {
                uint32_t a0, a1, a2, a3;
                ldsm4(a0, a1, a2, a3, a_ldm + bufoff + (uint32_t)(mi * 16 * AW) * 4);
#pragma unroll
                for (int ni = 0; ni < 4; ni++)
                    mma16816(acc[mi][ni], a0, a1, a2, a3, bf[ni][0], bf[ni][1]);
            }
        }
        av0 = nv0; av1 = nv1;
    }

    // epilogue: write split-K partials
#pragma unroll
    for (int mi = 0; mi < 4; mi++) {
#pragma unroll
        for (int ni = 0; ni < 4; ni++) {
            int row = m0 + wm * 64 + mi * 16 + r4;
            int col = n0 + wn * 32 + ni * 8 + q * 2;
            *(float2*)&g_part[sp][row][col]     = make_float2(acc[mi][ni][0], acc[mi][ni][1]);
            *(float2*)&g_part[sp][row + 8][col] = make_float2(acc[mi][ni][2], acc[mi][ni][3]);
        }
    }
}

// ---------------------------------------------------------------------------
__global__ void reduce_bias_relu(const float* __restrict__ cmd,
                                 const float* __restrict__ hbW,
                                 const float* __restrict__ hbb,
                                 float* dst, int dst_is_buf1) {
    int idx = blockIdx.x * blockDim.x + threadIdx.x;
    int b = idx >> 9;
    int o = idx & 511;
    float s = hbb[o];
#pragma unroll
    for (int sp = 0; sp < SPLITS; sp++) s += g_part[sp][b][o];
    const float* cp = cmd + b * DES;
#pragma unroll 16
    for (int k = 0; k < DES; k++)
        s = fmaf(cp[k], hbW[k * H + o], s);
    float r = fmaxf(s, 0.0f);
    if (dst_is_buf1) g_buf1[idx] = r;
    else             dst[idx] = r;
}

// ---------------------------------------------------------------------------
extern "C" void kernel_launch(void* const* d_in, const int* in_sizes, int n_in,
                              void* d_out, int out_size) {
    const float* state = (const float*)d_in[0];
    const float* cmd   = (const float*)d_in[1];
    const float* ew    = (const float*)d_in[2];
    const float* eb    = (const float*)d_in[3];
    const float* hwW   = (const float*)d_in[4];
    const float* hwb   = (const float*)d_in[5];
    const float* hbW   = (const float*)d_in[6];
    const float* hbb   = (const float*)d_in[7];
    float* out = (float*)d_out;

    const size_t HWW_L = (size_t)DES * H * H;
    const size_t HWB_L = (size_t)H * H;
    const size_t HBW_L = (size_t)DES * H;
    const size_t HBB_L = (size_t)H;

    static int smem_set = 0;
    if (!smem_set) {
        cudaFuncSetAttribute(gemm_fp16, cudaFuncAttributeMaxDynamicSharedMemorySize, SMEM_BYTES);
        smem_set = 1;
    }

    embed_kernel<<<1024, 256>>>(state, ew, eb);

    dim3 grid(4, 4, SPLITS);

    gemm_fp16<<<grid, 256, SMEM_BYTES>>>(0, cmd, hwW, hwb);
    reduce_bias_relu<<<1024, 256>>>(cmd, hbW, hbb, out, 1);

    gemm_fp16<<<grid, 256, SMEM_BYTES>>>(1, cmd, hwW + HWW_L, hwb + HWB_L);
    reduce_bias_relu<<<1024, 256>>>(cmd, hbW + HBW_L, hbb + HBB_L, out, 0);
}

// round 11
// speedup vs baseline: 1.0425x; 1.0425x over previous
#include <cuda_runtime.h>
#include <cstdint>
#include <math.h>

#define BB    512
#define STATE 256
#define DES   128
#define H     512
#define SPLITS 18
#define STG   8     // B ring stages
#define SBW   140   // sB row stride (words) -> conflict-free B frag LDS

#define SSC_F 1024                         // scale table floats (8 chunks x 16 recs x 8)
#define SMEM_F (SSC_F + STG * 16 * SBW)
#define SMEM_BYTES (SMEM_F * 4)            // 75776 -> 2 CTAs/SM (151.5KB < 228KB)

__device__ float g_buf0[BB * H];
__device__ float g_buf1[BB * H];
__device__ float g_part[SPLITS][BB][H];

__device__ __forceinline__ uint32_t pack_h2(float lo, float hi) {
    uint32_t r;
    asm("cvt.rn.f16x2.f32 %0, %1, %2;" : "=r"(r) : "f"(hi), "f"(lo));
    return r;
}
__device__ __forceinline__ void mma16816(float* c,
                                         uint32_t a0, uint32_t a1, uint32_t a2, uint32_t a3,
                                         uint32_t b0, uint32_t b1) {
    asm volatile("mma.sync.aligned.m16n8k16.row.col.f32.f16.f16.f32 "
                 "{%0,%1,%2,%3}, {%4,%5,%6,%7}, {%8,%9}, {%0,%1,%2,%3};"
                 : "+f"(c[0]), "+f"(c[1]), "+f"(c[2]), "+f"(c[3])
                 : "r"(a0), "r"(a1), "r"(a2), "r"(a3), "r"(b0), "r"(b1));
}
__device__ __forceinline__ uint32_t smem_u32(const void* p) {
    uint32_t a;
    asm("{ .reg .u64 t; cvta.to.shared.u64 t, %1; cvt.u32.u64 %0, t; }" : "=r"(a) : "l"(p));
    return a;
}
__device__ __forceinline__ void cp16(uint32_t dst, const float* src) {
    asm volatile("cp.async.cg.shared.global [%0], [%1], 16;" :: "r"(dst), "l"(src));
}
#define CP_COMMIT() asm volatile("cp.async.commit_group;" ::: "memory")
#define CP_WAIT6()  asm volatile("cp.async.wait_group 6;" ::: "memory")

// ---------------------------------------------------------------------------
__global__ void embed_kernel(const float* __restrict__ state,
                             const float* __restrict__ ew,
                             const float* __restrict__ eb) {
    int idx = blockIdx.x * blockDim.x + threadIdx.x;
    int b = idx >> 9;
    int j = idx & 511;
    float s = eb[j];
    const float* sp = state + b * STATE;
#pragma unroll 8
    for (int k = 0; k < STATE; k++)
        s = fmaf(sp[k], ew[k * H + j], s);
    g_buf0[idx] = tanhf(s);
}

// ---------------------------------------------------------------------------
// fp16 m16n8k16 split-K GEMM.
//   - A fragments: unscaled fp32 in REGISTERS, loaded from gmem once per k-band
//   - per-chunk scale applied at pack time (rn16(a*s), same numerics as before)
//   - B: 8-stage cp.async ring (identical to prior round)
//   virtual A[b, d*512+h] = cmd[b,d] * in[b,h]   (chunk d=128 -> hw_b, scale 1)
// ---------------------------------------------------------------------------
__global__ void __launch_bounds__(256, 2)
gemm_fp16(int layer, const float* __restrict__ cmd,
          const float* __restrict__ hwW, const float* __restrict__ hwb)
{
    extern __shared__ __align__(16) float smf[];
    float* sSc = smf;                 // [cnt][16 recs][8 floats]
    float* sB  = smf + SSC_F;

    const int t    = threadIdx.x;
    const int lane = t & 31;
    const int w    = t >> 5;
    const int wm   = w & 1;
    const int wn   = w >> 1;
    const int q    = lane & 3;
    const int r4   = lane >> 2;

    const int n0 = blockIdx.x * 128;
    const int m0 = blockIdx.y * 128;
    const int sp = blockIdx.z;
    const int c0  = sp * 7 + (sp < 3 ? sp : 3);
    const int cnt = 7 + (sp < 3 ? 1 : 0);

    const float* __restrict__ inbuf = layer ? g_buf1 : g_buf0;

    // ---- stage scale table: record (ci, wm*8+r4) = 8 floats {s(row), s(row+8)}x4mi
    if (t < cnt * 16) {
        int ci = t >> 4, rec = t & 15;
        int wmv = rec >> 3, rv = rec & 7;
        int d = c0 + ci;
        float* dst = sSc + (size_t)t * 8;
#pragma unroll
        for (int mi = 0; mi < 4; mi++) {
            int row0 = m0 + wmv * 64 + mi * 16 + rv;
            dst[mi * 2]     = (d < DES) ? cmd[row0 * DES + d] : 1.0f;
            dst[mi * 2 + 1] = (d < DES) ? cmd[(row0 + 8) * DES + d] : 1.0f;
        }
    }

    // ---- B cp.async roles ----
    const int brow = t >> 5;
    const int bcol4 = (t & 31) * 4;
    const uint32_t sB_u32 = smem_u32(sB);
    const uint32_t bdst1 = sB_u32 + (uint32_t)(brow * SBW + bcol4) * 4;
    const uint32_t bdst2 = bdst1 + 8 * SBW * 4;

    auto issueB = [&](int kbj, int cij, int slot) {
        int d = c0 + cij;
        const float* bb = ((d < DES) ? (hwW + (size_t)d * (H * H)) : hwb)
                          + ((size_t)kbj << 4) * H + n0;
        uint32_t so = (uint32_t)slot * (16 * SBW * 4);
        cp16(bdst1 + so, bb + brow * H + bcol4);
        cp16(bdst2 + so, bb + (brow + 8) * H + bcol4);
        CP_COMMIT();
    };

    float acc[4][4][4];
#pragma unroll
    for (int i = 0; i < 4; i++)
#pragma unroll
        for (int j = 0; j < 4; j++)
#pragma unroll
            for (int k = 0; k < 4; k++) acc[i][j][k] = 0.0f;

    // prologue: 7 B stages in flight (kb=0, ci=0..6; cnt>=7)
#pragma unroll
    for (int i = 0; i < 7; i++) issueB(0, i, i);
    int kb_is = 0, ci_is = 7;
    if (ci_is >= cnt) { ci_is -= cnt; kb_is = 1; }

    // A fragment base pointer (this thread's rows, k offset 2q)
    const float* aptr = inbuf + (size_t)(m0 + wm * 64 + r4) * H + 2 * q;
    const uint32_t screc = (uint32_t)(wm * 8 + r4) * 8;

    float2 auf[4][4];   // unscaled A frags: [mi]{(r,2q),(r+8,2q),(r,2q+8),(r+8,2q+8)}

    int it = 0;
    for (int kb = 0; kb < 32; kb++) {
        // ---- load A band from gmem into registers (L2-hot) ----
#pragma unroll
        for (int mi = 0; mi < 4; mi++) {
            const float* p = aptr + (size_t)(mi * 16) * H + kb * 16;
            auf[mi][0] = *(const float2*)(p);
            auf[mi][1] = *(const float2*)(p + 8 * H);
            auf[mi][2] = *(const float2*)(p + 8);
            auf[mi][3] = *(const float2*)(p + 8 * H + 8);
        }

        for (int ci = 0; ci < cnt; ci++, it++) {
            CP_WAIT6();
            __syncthreads();

            // keep ring full
            issueB(kb_is, ci_is, (it + 7) % STG);
            if (++ci_is == cnt) {
                ci_is = 0;
                if (++kb_is == 32) { kb_is = 31; ci_is = cnt - 1; }
            }

            // scale record: 2 broadcast LDS.128
            const float4* rec = (const float4*)(sSc + ((uint32_t)ci * 16 * 8 + screc));
            float4 s01 = rec[0];
            float4 s23 = rec[1];
            float sv[8] = {s01.x, s01.y, s01.z, s01.w, s23.x, s23.y, s23.z, s23.w};

            // B fragments (fp32 -> f16x2)
            const float* sb = sB + (it % STG) * (16 * SBW);
            uint32_t bf[4][2];
#pragma unroll
            for (int ni = 0; ni < 4; ni++) {
                int col = wn * 32 + ni * 8 + r4;
                float b0 = sb[(2 * q) * SBW + col];
                float b1 = sb[(2 * q + 1) * SBW + col];
                float b2 = sb[(2 * q + 8) * SBW + col];
                float b3 = sb[(2 * q + 9) * SBW + col];
                bf[ni][0] = pack_h2(b0, b1);
                bf[ni][1] = pack_h2(b2, b3);
            }

            // scaled A fragments + MMAs
#pragma unroll
            for (int mi = 0; mi < 4; mi++) {
                float s0 = sv[mi * 2], s1 = sv[mi * 2 + 1];
                uint32_t a0 = pack_h2(auf[mi][0].x * s0, auf[mi][0].y * s0);
                uint32_t a1 = pack_h2(auf[mi][1].x * s1, auf[mi][1].y * s1);
                uint32_t a2 = pack_h2(auf[mi][2].x * s0, auf[mi][2].y * s0);
                uint32_t a3 = pack_h2(auf[mi][3].x * s1, auf[mi][3].y * s1);
#pragma unroll
                for (int ni = 0; ni < 4; ni++)
                    mma16816(acc[mi][ni], a0, a1, a2, a3, bf[ni][0], bf[ni][1]);
            }
        }
    }

    // ---- epilogue: write split-K partials ----
#pragma unroll
    for (int mi = 0; mi < 4; mi++) {
#pragma unroll
        for (int ni = 0; ni < 4; ni++) {
            int row = m0 + wm * 64 + mi * 16 + r4;
            int col = n0 + wn * 32 + ni * 8 + q * 2;
            *(float2*)&g_part[sp][row][col]     = make_float2(acc[mi][ni][0], acc[mi][ni][1]);
            *(float2*)&g_part[sp][row + 8][col] = make_float2(acc[mi][ni][2], acc[mi][ni][3]);
        }
    }
}

// ---------------------------------------------------------------------------
__global__ void reduce_bias_relu(const float* __restrict__ cmd,
                                 const float* __restrict__ hbW,
                                 const float* __restrict__ hbb,
                                 float* dst, int dst_is_buf1) {
    int idx = blockIdx.x * blockDim.x + threadIdx.x;
    int b = idx >> 9;
    int o = idx & 511;
    float s = hbb[o];
#pragma unroll
    for (int sp = 0; sp < SPLITS; sp++) s += g_part[sp][b][o];
    const float* cp = cmd + b * DES;
#pragma unroll 16
    for (int k = 0; k < DES; k++)
        s = fmaf(cp[k], hbW[k * H + o], s);
    float r = fmaxf(s, 0.0f);
    if (dst_is_buf1) g_buf1[idx] = r;
    else             dst[idx] = r;
}

// ---------------------------------------------------------------------------
extern "C" void kernel_launch(void* const* d_in, const int* in_sizes, int n_in,
                              void* d_out, int out_size) {
    const float* state = (const float*)d_in[0];
    const float* cmd   = (const float*)d_in[1];
    const float* ew    = (const float*)d_in[2];
    const float* eb    = (const float*)d_in[3];
    const float* hwW   = (const float*)d_in[4];
    const float* hwb   = (const float*)d_in[5];
    const float* hbW   = (const float*)d_in[6];
    const float* hbb   = (const float*)d_in[7];
    float* out = (float*)d_out;

    const size_t HWW_L = (size_t)DES * H * H;
    const size_t HWB_L = (size_t)H * H;
    const size_t HBW_L = (size_t)DES * H;
    const size_t HBB_L = (size_t)H;

    static int smem_set = 0;
    if (!smem_set) {
        cudaFuncSetAttribute(gemm_fp16, cudaFuncAttributeMaxDynamicSharedMemorySize, SMEM_BYTES);
        smem_set = 1;
    }

    embed_kernel<<<1024, 256>>>(state, ew, eb);

    dim3 grid(4, 4, SPLITS);

    gemm_fp16<<<grid, 256, SMEM_BYTES>>>(0, cmd, hwW, hwb);
    reduce_bias_relu<<<1024, 256>>>(cmd, hbW, hbb, out, 1);

    gemm_fp16<<<grid, 256, SMEM_BYTES>>>(1, cmd, hwW + HWW_L, hwb + HWB_L);
    reduce_bias_relu<<<1024, 256>>>(cmd, hbW + HBW_L, hbb + HBB_L, out, 0);
}

// round 12
// speedup vs baseline: 1.1717x; 1.1239x over previous
#include <cuda_runtime.h>
#include <cuda_fp16.h>
#include <cstdint>
#include <math.h>

#define BB    512
#define STATE 256
#define DES   128
#define H     512
#define SPLITS 18
#define STG   8     // B ring stages
#define SBW   140   // sB row stride (words) -> conflict-free B frag LDS

#define SSC_U 1024                         // scale table u32 (8 chunks x 16 recs x 8)
#define SMEM_U (SSC_U + STG * 16 * SBW)
#define SMEM_BYTES (SMEM_U * 4)            // 75776 -> 2 CTAs/SM

__device__ uint32_t g_h0[BB * H / 2];      // fp16x2 activations (k-pairs), layer-0 input
__device__ uint32_t g_h1[BB * H / 2];      // layer-1 input
__device__ float g_part[SPLITS][BB][H];

__device__ __forceinline__ uint32_t pack_h2(float lo, float hi) {
    uint32_t r;
    asm("cvt.rn.f16x2.f32 %0, %1, %2;" : "=r"(r) : "f"(hi), "f"(lo));
    return r;
}
__device__ __forceinline__ uint32_t hmul2(uint32_t a, uint32_t b) {
    uint32_t r;
    asm("mul.rn.f16x2 %0, %1, %2;" : "=r"(r) : "r"(a), "r"(b));
    return r;
}
__device__ __forceinline__ uint32_t dup_h2(float s) {
    uint32_t r;
    asm("{ .reg .b16 h; cvt.rn.f16.f32 h, %1; mov.b32 %0, {h, h}; }" : "=r"(r) : "f"(s));
    return r;
}
__device__ __forceinline__ void mma16816(float* c,
                                         uint32_t a0, uint32_t a1, uint32_t a2, uint32_t a3,
                                         uint32_t b0, uint32_t b1) {
    asm volatile("mma.sync.aligned.m16n8k16.row.col.f32.f16.f16.f32 "
                 "{%0,%1,%2,%3}, {%4,%5,%6,%7}, {%8,%9}, {%0,%1,%2,%3};"
                 : "+f"(c[0]), "+f"(c[1]), "+f"(c[2]), "+f"(c[3])
                 : "r"(a0), "r"(a1), "r"(a2), "r"(a3), "r"(b0), "r"(b1));
}
__device__ __forceinline__ uint32_t smem_u32(const void* p) {
    uint32_t a;
    asm("{ .reg .u64 t; cvta.to.shared.u64 t, %1; cvt.u32.u64 %0, t; }" : "=r"(a) : "l"(p));
    return a;
}
__device__ __forceinline__ void cp16(uint32_t dst, const float* src) {
    asm volatile("cp.async.cg.shared.global [%0], [%1], 16;" :: "r"(dst), "l"(src));
}
#define CP_COMMIT() asm volatile("cp.async.commit_group;" ::: "memory")
#define CP_WAIT6()  asm volatile("cp.async.wait_group 6;" ::: "memory")

// ---------------------------------------------------------------------------
// Embed: writes fp16x2 activations directly. Thread handles j-pair (2j, 2j+1).
// ---------------------------------------------------------------------------
__global__ void embed_kernel(const float* __restrict__ state,
                             const float* __restrict__ ew,
                             const float* __restrict__ eb) {
    int idx = blockIdx.x * blockDim.x + threadIdx.x;   // 0 .. BB*H/2-1
    int b = idx >> 8;
    int j = (idx & 255) * 2;
    float s0 = eb[j], s1 = eb[j + 1];
    const float* sp = state + b * STATE;
#pragma unroll 8
    for (int k = 0; k < STATE; k++) {
        float sv = sp[k];
        s0 = fmaf(sv, ew[k * H + j], s0);
        s1 = fmaf(sv, ew[k * H + j + 1], s1);
    }
    g_h0[idx] = pack_h2(tanhf(s0), tanhf(s1));
}

// ---------------------------------------------------------------------------
// fp16 m16n8k16 split-K GEMM.
//   - A: fp16x2 activations in registers, loaded from gmem once per k-band
//   - per-chunk scale applied as HMUL2 at pack time (dup-h2 scale table in smem)
//   - B: 8-stage cp.async ring
// ---------------------------------------------------------------------------
__global__ void __launch_bounds__(256, 2)
gemm_fp16(int layer, const float* __restrict__ cmd,
          const float* __restrict__ hwW, const float* __restrict__ hwb)
{
    extern __shared__ __align__(16) uint32_t smu[];
    uint32_t* sSc = smu;              // [cnt][16 recs][8 u32]
    float* sB = (float*)(smu + SSC_U);

    const int t    = threadIdx.x;
    const int lane = t & 31;
    const int w    = t >> 5;
    const int wm   = w & 1;
    const int wn   = w >> 1;
    const int q    = lane & 3;
    const int r4   = lane >> 2;

    const int n0 = blockIdx.x * 128;
    const int m0 = blockIdx.y * 128;
    const int sp = blockIdx.z;
    const int c0  = sp * 7 + (sp < 3 ? sp : 3);
    const int cnt = 7 + (sp < 3 ? 1 : 0);

    const uint32_t* __restrict__ inh = layer ? g_h1 : g_h0;

    // ---- scale table: rec(ci, wm*8+r4) = 8 u32 {h2(s0,s0), h2(s1,s1)} x 4mi ----
    if (t < cnt * 16) {
        int ci = t >> 4, rec = t & 15;
        int wmv = rec >> 3, rv = rec & 7;
        int d = c0 + ci;
        uint32_t* dst = sSc + (size_t)t * 8;
#pragma unroll
        for (int mi = 0; mi < 4; mi++) {
            int row0 = m0 + wmv * 64 + mi * 16 + rv;
            dst[mi * 2]     = dup_h2((d < DES) ? cmd[row0 * DES + d] : 1.0f);
            dst[mi * 2 + 1] = dup_h2((d < DES) ? cmd[(row0 + 8) * DES + d] : 1.0f);
        }
    }

    // ---- B cp.async roles ----
    const int brow = t >> 5;
    const int bcol4 = (t & 31) * 4;
    const uint32_t sB_u32 = smem_u32(sB);
    const uint32_t bdst1 = sB_u32 + (uint32_t)(brow * SBW + bcol4) * 4;
    const uint32_t bdst2 = bdst1 + 8 * SBW * 4;

    auto issueB = [&](int kbj, int cij, int slot) {
        int d = c0 + cij;
        const float* bb = ((d < DES) ? (hwW + (size_t)d * (H * H)) : hwb)
                          + ((size_t)kbj << 4) * H + n0;
        uint32_t so = (uint32_t)slot * (16 * SBW * 4);
        cp16(bdst1 + so, bb + brow * H + bcol4);
        cp16(bdst2 + so, bb + (brow + 8) * H + bcol4);
        CP_COMMIT();
    };

    float acc[4][4][4];
#pragma unroll
    for (int i = 0; i < 4; i++)
#pragma unroll
        for (int j = 0; j < 4; j++)
#pragma unroll
            for (int k = 0; k < 4; k++) acc[i][j][k] = 0.0f;

    // prologue: 7 B stages in flight
#pragma unroll
    for (int i = 0; i < 7; i++) issueB(0, i, i);
    int kb_is = 0, ci_is = 7;
    if (ci_is >= cnt) { ci_is -= cnt; kb_is = 1; }

    // A fragment base (h2 index): row*(H/2) + q, band offset kb*8
    const uint32_t* aptr = inh + (size_t)(m0 + wm * 64 + r4) * (H / 2) + q;
    const uint32_t screc = (uint32_t)(wm * 8 + r4) * 8;

    uint32_t auf[4][4];   // unscaled h2 A frags

    int it = 0;
    for (int kb = 0; kb < 32; kb++) {
        // ---- load A band (h2) from gmem (L2-hot) ----
#pragma unroll
        for (int mi = 0; mi < 4; mi++) {
            const uint32_t* p = aptr + (size_t)(mi * 16) * (H / 2) + kb * 8;
            auf[mi][0] = p[0];
            auf[mi][1] = p[8 * (H / 2)];
            auf[mi][2] = p[4];
            auf[mi][3] = p[8 * (H / 2) + 4];
        }

        for (int ci = 0; ci < cnt; ci++, it++) {
            CP_WAIT6();
            __syncthreads();

            issueB(kb_is, ci_is, (it + 7) % STG);
            if (++ci_is == cnt) {
                ci_is = 0;
                if (++kb_is == 32) { kb_is = 31; ci_is = cnt - 1; }
            }

            // scale record: 2 broadcast LDS.128 (8 dup-h2)
            const uint4* rec = (const uint4*)(sSc + ((uint32_t)ci * 16 * 8 + screc));
            uint4 sA01 = rec[0];
            uint4 sA23 = rec[1];
            uint32_t sv[8] = {sA01.x, sA01.y, sA01.z, sA01.w,
                              sA23.x, sA23.y, sA23.z, sA23.w};

            // B fragments (fp32 -> f16x2)
            const float* sb = sB + (it % STG) * (16 * SBW);
            uint32_t bf[4][2];
#pragma unroll
            for (int ni = 0; ni < 4; ni++) {
                int col = wn * 32 + ni * 8 + r4;
                float b0 = sb[(2 * q) * SBW + col];
                float b1 = sb[(2 * q + 1) * SBW + col];
                float b2 = sb[(2 * q + 8) * SBW + col];
                float b3 = sb[(2 * q + 9) * SBW + col];
                bf[ni][0] = pack_h2(b0, b1);
                bf[ni][1] = pack_h2(b2, b3);
            }

            // scaled A fragments (HMUL2) + MMAs
#pragma unroll
            for (int mi = 0; mi < 4; mi++) {
                uint32_t s0 = sv[mi * 2], s1 = sv[mi * 2 + 1];
                uint32_t a0 = hmul2(auf[mi][0], s0);
                uint32_t a1 = hmul2(auf[mi][1], s1);
                uint32_t a2 = hmul2(auf[mi][2], s0);
                uint32_t a3 = hmul2(auf[mi][3], s1);
#pragma unroll
                for (int ni = 0; ni < 4; ni++)
                    mma16816(acc[mi][ni], a0, a1, a2, a3, bf[ni][0], bf[ni][1]);
            }
        }
    }

    // ---- epilogue ----
#pragma unroll
    for (int mi = 0; mi < 4; mi++) {
#pragma unroll
        for (int ni = 0; ni < 4; ni++) {
            int row = m0 + wm * 64 + mi * 16 + r4;
            int col = n0 + wn * 32 + ni * 8 + q * 2;
            *(float2*)&g_part[sp][row][col]     = make_float2(acc[mi][ni][0], acc[mi][ni][1]);
            *(float2*)&g_part[sp][row + 8][col] = make_float2(acc[mi][ni][2], acc[mi][ni][3]);
        }
    }
}

// ---------------------------------------------------------------------------
// Reduce split-K partials + (c @ hb_W + hb_b) + ReLU.
// Thread handles o-pair (2j, 2j+1). mode0: write g_h1 (h2); mode1: write fp32 out.
// ---------------------------------------------------------------------------
__global__ void reduce_bias_relu(const float* __restrict__ cmd,
                                 const float* __restrict__ hbW,
                                 const float* __restrict__ hbb,
                                 float* dst, int to_h1) {
    int idx = blockIdx.x * blockDim.x + threadIdx.x;   // 0 .. BB*H/2-1
    int b = idx >> 8;
    int o = (idx & 255) * 2;
    float s0 = hbb[o], s1 = hbb[o + 1];
#pragma unroll
    for (int sp = 0; sp < SPLITS; sp++) {
        float2 v = *(const float2*)&g_part[sp][b][o];
        s0 += v.x; s1 += v.y;
    }
    const float* cp = cmd + b * DES;
#pragma unroll 16
    for (int k = 0; k < DES; k++) {
        float cv = cp[k];
        s0 = fmaf(cv, hbW[k * H + o], s0);
        s1 = fmaf(cv, hbW[k * H + o + 1], s1);
    }
    float r0 = fmaxf(s0, 0.0f);
    float r1 = fmaxf(s1, 0.0f);
    if (to_h1) {
        g_h1[idx] = pack_h2(r0, r1);
    } else {
        *(float2*)&dst[b * H + o] = make_float2(r0, r1);
    }
}

// ---------------------------------------------------------------------------
extern "C" void kernel_launch(void* const* d_in, const int* in_sizes, int n_in,
                              void* d_out, int out_size) {
    const float* state = (const float*)d_in[0];
    const float* cmd   = (const float*)d_in[1];
    const float* ew    = (const float*)d_in[2];
    const float* eb    = (const float*)d_in[3];
    const float* hwW   = (const float*)d_in[4];
    const float* hwb   = (const float*)d_in[5];
    const float* hbW   = (const float*)d_in[6];
    const float* hbb   = (const float*)d_in[7];
    float* out = (float*)d_out;

    const size_t HWW_L = (size_t)DES * H * H;
    const size_t HWB_L = (size_t)H * H;
    const size_t HBW_L = (size_t)DES * H;
    const size_t HBB_L = (size_t)H;

    static int smem_set = 0;
    if (!smem_set) {
        cudaFuncSetAttribute(gemm_fp16, cudaFuncAttributeMaxDynamicSharedMemorySize, SMEM_BYTES);
        smem_set = 1;
    }

    embed_kernel<<<512, 256>>>(state, ew, eb);

    dim3 grid(4, 4, SPLITS);

    gemm_fp16<<<grid, 256, SMEM_BYTES>>>(0, cmd, hwW, hwb);
    reduce_bias_relu<<<512, 256>>>(cmd, hbW, hbb, out, 1);

    gemm_fp16<<<grid, 256, SMEM_BYTES>>>(1, cmd, hwW + HWW_L, hwb + HWB_L);
    reduce_bias_relu<<<512, 256>>>(cmd, hbW + HBW_L, hbb + HBB_L, out, 0);
}

// round 13
// speedup vs baseline: 1.2012x; 1.0251x over previous
#include <cuda_runtime.h>
#include <cuda_fp16.h>
#include <cstdint>
#include <math.h>

#define BB    512
#define STATE 256
#define DES   128
#define H     512
#define SPLITS 18
#define STG   8      // fp32 B ring stages (thread-private roundtrip)

// smem layout (bytes from base):
//   [0, 4096)        scale table (8 chunks x 16 recs x 8 u32)
//   [4096, 69632)    fp32 B ring: STG x 16 x 128 f32 (8KB/stage)
//   [69632, 82688)   fp16 B tiles: 3 x 16 x 136 h2-cols... (16 rows x 272B = 4352B each)
#define SC_BYTES   4096
#define RING_OFF   SC_BYTES
#define STAGE_B    (16 * 128 * 4)        // 8192
#define H2_OFF     (RING_OFF + STG * STAGE_B)   // 69632
#define H2_STAGE   (16 * 272)            // 4352
#define SMEM_BYTES (H2_OFF + 3 * H2_STAGE)      // 82688 -> 2 CTAs/SM

__device__ uint32_t g_h0[BB * H / 2];
__device__ uint32_t g_h1[BB * H / 2];
__device__ float g_part[SPLITS][BB][H];

__device__ __forceinline__ uint32_t pack_h2(float lo, float hi) {
    uint32_t r;
    asm("cvt.rn.f16x2.f32 %0, %1, %2;" : "=r"(r) : "f"(hi), "f"(lo));
    return r;
}
__device__ __forceinline__ uint32_t hmul2(uint32_t a, uint32_t b) {
    uint32_t r;
    asm("mul.rn.f16x2 %0, %1, %2;" : "=r"(r) : "r"(a), "r"(b));
    return r;
}
__device__ __forceinline__ uint32_t dup_h2(float s) {
    uint32_t r;
    asm("{ .reg .b16 h; cvt.rn.f16.f32 h, %1; mov.b32 %0, {h, h}; }" : "=r"(r) : "f"(s));
    return r;
}
__device__ __forceinline__ void mma16816(float* c,
                                         uint32_t a0, uint32_t a1, uint32_t a2, uint32_t a3,
                                         uint32_t b0, uint32_t b1) {
    asm volatile("mma.sync.aligned.m16n8k16.row.col.f32.f16.f16.f32 "
                 "{%0,%1,%2,%3}, {%4,%5,%6,%7}, {%8,%9}, {%0,%1,%2,%3};"
                 : "+f"(c[0]), "+f"(c[1]), "+f"(c[2]), "+f"(c[3])
                 : "r"(a0), "r"(a1), "r"(a2), "r"(a3), "r"(b0), "r"(b1));
}
__device__ __forceinline__ uint32_t smem_u32(const void* p) {
    uint32_t a;
    asm("{ .reg .u64 t; cvta.to.shared.u64 t, %1; cvt.u32.u64 %0, t; }" : "=r"(a) : "l"(p));
    return a;
}
__device__ __forceinline__ void cp16(uint32_t dst, const float* src) {
    asm volatile("cp.async.cg.shared.global [%0], [%1], 16;" :: "r"(dst), "l"(src));
}
__device__ __forceinline__ float4 lds128f(uint32_t a) {
    float4 v;
    asm volatile("ld.shared.v4.f32 {%0,%1,%2,%3}, [%4];"
                 : "=f"(v.x), "=f"(v.y), "=f"(v.z), "=f"(v.w) : "r"(a));
    return v;
}
__device__ __forceinline__ void sts64(uint32_t a, uint32_t x, uint32_t y) {
    asm volatile("st.shared.v2.b32 [%0], {%1,%2};" :: "r"(a), "r"(x), "r"(y) : "memory");
}
__device__ __forceinline__ void ldsm4t(uint32_t& b0, uint32_t& b1, uint32_t& b2, uint32_t& b3,
                                       uint32_t addr) {
    asm volatile("ldmatrix.sync.aligned.m8n8.x4.trans.shared.b16 {%0,%1,%2,%3}, [%4];"
                 : "=r"(b0), "=r"(b1), "=r"(b2), "=r"(b3) : "r"(addr));
}
#define CP_COMMIT() asm volatile("cp.async.commit_group;" ::: "memory")
#define CP_WAIT5()  asm volatile("cp.async.wait_group 5;" ::: "memory")
#define CP_WAIT6()  asm volatile("cp.async.wait_group 6;" ::: "memory")

// ---------------------------------------------------------------------------
__global__ void embed_kernel(const float* __restrict__ state,
                             const float* __restrict__ ew,
                             const float* __restrict__ eb) {
    int idx = blockIdx.x * blockDim.x + threadIdx.x;
    int b = idx >> 8;
    int j = (idx & 255) * 2;
    float s0 = eb[j], s1 = eb[j + 1];
    const float* sp = state + b * STATE;
#pragma unroll 8
    for (int k = 0; k < STATE; k++) {
        float sv = sp[k];
        s0 = fmaf(sv, ew[k * H + j], s0);
        s1 = fmaf(sv, ew[k * H + j + 1], s1);
    }
    g_h0[idx] = pack_h2(tanhf(s0), tanhf(s1));
}

// ---------------------------------------------------------------------------
// fp16 m16n8k16 split-K GEMM.
//  - A: h2 activations in regs (one gmem load per k-band), scaled by HMUL2
//  - B: cp.async fp32 ring (thread-private roundtrip) -> per-iter single-pass
//       conversion into triple-buffered fp16 tile -> 2x ldmatrix.x4.trans
// ---------------------------------------------------------------------------
__global__ void __launch_bounds__(256, 2)
gemm_fp16(int layer, const float* __restrict__ cmd,
          const float* __restrict__ hwW, const float* __restrict__ hwb)
{
    extern __shared__ __align__(16) uint32_t smu[];
    uint32_t* sSc = smu;

    const int t    = threadIdx.x;
    const int lane = t & 31;
    const int w    = t >> 5;
    const int wm   = w & 1;
    const int wn   = w >> 1;
    const int q    = lane & 3;
    const int r4   = lane >> 2;

    const int n0 = blockIdx.x * 128;
    const int m0 = blockIdx.y * 128;
    const int sp = blockIdx.z;
    const int c0  = sp * 7 + (sp < 3 ? sp : 3);
    const int cnt = 7 + (sp < 3 ? 1 : 0);

    const uint32_t* __restrict__ inh = layer ? g_h1 : g_h0;

    // ---- scale table ----
    if (t < cnt * 16) {
        int ci = t >> 4, rec = t & 15;
        int wmv = rec >> 3, rv = rec & 7;
        int d = c0 + ci;
        uint32_t* dst = sSc + (size_t)t * 8;
#pragma unroll
        for (int mi = 0; mi < 4; mi++) {
            int row0 = m0 + wmv * 64 + mi * 16 + rv;
            dst[mi * 2]     = dup_h2((d < DES) ? cmd[row0 * DES + d] : 1.0f);
            dst[mi * 2 + 1] = dup_h2((d < DES) ? cmd[(row0 + 8) * DES + d] : 1.0f);
        }
    }

    const uint32_t base = smem_u32(smu);

    // ---- fp32 ring roles (thread-private) ----
    const int brow = t >> 5;
    const int bcol4 = (t & 31) * 4;
    const uint32_t rdst1 = base + RING_OFF + (uint32_t)(brow * 128 + bcol4) * 4;
    const uint32_t rdst2 = rdst1 + 8 * 128 * 4;

    // ---- h2 tile addresses ----
    const uint32_t h2b = base + H2_OFF;
    const uint32_t csts1 = h2b + (uint32_t)brow * 272 + (uint32_t)bcol4 * 2;
    const uint32_t csts2 = csts1 + 8 * 272;
    // ldmatrix lane address
    const int sel = lane >> 3;
    const int krow = ((sel & 1) << 3) | (lane & 7);
    const int nbl  = wn * 32 + ((sel >> 1) << 3);
    const uint32_t ldm0 = h2b + (uint32_t)krow * 272 + (uint32_t)nbl * 2;

    auto issueB = [&](int kbj, int cij, int slot) {
        int d = c0 + cij;
        const float* bb = ((d < DES) ? (hwW + (size_t)d * (H * H)) : hwb)
                          + ((size_t)kbj << 4) * H + n0;
        uint32_t so = (uint32_t)slot * STAGE_B;
        cp16(rdst1 + so, bb + brow * H + bcol4);
        cp16(rdst2 + so, bb + (brow + 8) * H + bcol4);
        CP_COMMIT();
    };
    auto convert = [&](int slot, int buf3) {
        uint32_t so = (uint32_t)slot * STAGE_B;
        uint32_t bo = (uint32_t)buf3 * H2_STAGE;
        float4 v1 = lds128f(rdst1 + so);
        float4 v2 = lds128f(rdst2 + so);
        sts64(csts1 + bo, pack_h2(v1.x, v1.y), pack_h2(v1.z, v1.w));
        sts64(csts2 + bo, pack_h2(v2.x, v2.y), pack_h2(v2.z, v2.w));
    };

    float acc[4][4][4];
#pragma unroll
    for (int i = 0; i < 4; i++)
#pragma unroll
        for (int j = 0; j < 4; j++)
#pragma unroll
            for (int k = 0; k < 4; k++) acc[i][j][k] = 0.0f;

    // prologue: 7 stages in flight; convert stage 0 into h2 buf 0
#pragma unroll
    for (int i = 0; i < 7; i++) issueB(0, i, i);
    int kb_is = 0, ci_is = 7;
    if (ci_is >= cnt) { ci_is -= cnt; kb_is = 1; }
    CP_WAIT6();
    convert(0, 0);

    const uint32_t* aptr = inh + (size_t)(m0 + wm * 64 + r4) * (H / 2) + q;
    const uint32_t screc = (uint32_t)(wm * 8 + r4) * 8;

    uint32_t auf[4][4];
    int it = 0;
    int cur3 = 0, nxt3 = 1;

    for (int kb = 0; kb < 32; kb++) {
        // A band (h2) from gmem (L2-hot)
#pragma unroll
        for (int mi = 0; mi < 4; mi++) {
            const uint32_t* p = aptr + (size_t)(mi * 16) * (H / 2) + kb * 8;
            auf[mi][0] = p[0];
            auf[mi][1] = p[8 * (H / 2)];
            auf[mi][2] = p[4];
            auf[mi][3] = p[8 * (H / 2) + 4];
        }

        for (int ci = 0; ci < cnt; ci++, it++) {
            // convert stage it+1 into h2 buf nxt3 (thread-private fp32 read)
            CP_WAIT5();
            convert((it + 1) % STG, nxt3);

            __syncthreads();

            issueB(kb_is, ci_is, (it + 7) % STG);
            if (++ci_is == cnt) {
                ci_is = 0;
                if (++kb_is == 32) { kb_is = 31; ci_is = cnt - 1; }
            }

            // scale record
            const uint4* rec = (const uint4*)(sSc + ((uint32_t)ci * 16 * 8 + screc));
            uint4 sA01 = rec[0];
            uint4 sA23 = rec[1];
            uint32_t sv[8] = {sA01.x, sA01.y, sA01.z, sA01.w,
                              sA23.x, sA23.y, sA23.z, sA23.w};

            // B fragments: 2x ldmatrix.x4.trans from h2 buf cur3
            uint32_t bf[4][2];
            {
                uint32_t a0 = ldm0 + (uint32_t)cur3 * H2_STAGE;
                ldsm4t(bf[0][0], bf[0][1], bf[1][0], bf[1][1], a0);
                ldsm4t(bf[2][0], bf[2][1], bf[3][0], bf[3][1], a0 + 32);
            }

            // scaled A + MMAs
#pragma unroll
            for (int mi = 0; mi < 4; mi++) {
                uint32_t s0 = sv[mi * 2], s1 = sv[mi * 2 + 1];
                uint32_t a0 = hmul2(auf[mi][0], s0);
                uint32_t a1 = hmul2(auf[mi][1], s1);
                uint32_t a2 = hmul2(auf[mi][2], s0);
                uint32_t a3 = hmul2(auf[mi][3], s1);
#pragma unroll
                for (int ni = 0; ni < 4; ni++)
                    mma16816(acc[mi][ni], a0, a1, a2, a3, bf[ni][0], bf[ni][1]);
            }

            cur3 = nxt3;
            nxt3 = (nxt3 == 2) ? 0 : nxt3 + 1;
        }
    }

    // epilogue
#pragma unroll
    for (int mi = 0; mi < 4; mi++) {
#pragma unroll
        for (int ni = 0; ni < 4; ni++) {
            int row = m0 + wm * 64 + mi * 16 + r4;
            int col = n0 + wn * 32 + ni * 8 + q * 2;
            *(float2*)&g_part[sp][row][col]     = make_float2(acc[mi][ni][0], acc[mi][ni][1]);
            *(float2*)&g_part[sp][row + 8][col] = make_float2(acc[mi][ni][2], acc[mi][ni][3]);
        }
    }
}

// ---------------------------------------------------------------------------
__global__ void reduce_bias_relu(const float* __restrict__ cmd,
                                 const float* __restrict__ hbW,
                                 const float* __restrict__ hbb,
                                 float* dst, int to_h1) {
    int idx = blockIdx.x * blockDim.x + threadIdx.x;
    int b = idx >> 8;
    int o = (idx & 255) * 2;
    float s0 = hbb[o], s1 = hbb[o + 1];
#pragma unroll
    for (int sp = 0; sp < SPLITS; sp++) {
        float2 v = *(const float2*)&g_part[sp][b][o];
        s0 += v.x; s1 += v.y;
    }
    const float* cp = cmd + b * DES;
#pragma unroll 16
    for (int k = 0; k < DES; k++) {
        float cv = cp[k];
        s0 = fmaf(cv, hbW[k * H + o], s0);
        s1 = fmaf(cv, hbW[k * H + o + 1], s1);
    }
    float r0 = fmaxf(s0, 0.0f);
    float r1 = fmaxf(s1, 0.0f);
    if (to_h1) {
        g_h1[idx] = pack_h2(r0, r1);
    } else {
        *(float2*)&dst[b * H + o] = make_float2(r0, r1);
    }
}

// ---------------------------------------------------------------------------
extern "C" void kernel_launch(void* const* d_in, const int* in_sizes, int n_in,
                              void* d_out, int out_size) {
    const float* state = (const float*)d_in[0];
    const float* cmd   = (const float*)d_in[1];
    const float* ew    = (const float*)d_in[2];
    const float* eb    = (const float*)d_in[3];
    const float* hwW   = (const float*)d_in[4];
    const float* hwb   = (const float*)d_in[5];
    const float* hbW   = (const float*)d_in[6];
    const float* hbb   = (const float*)d_in[7];
    float* out = (float*)d_out;

    const size_t HWW_L = (size_t)DES * H * H;
    const size_t HWB_L = (size_t)H * H;
    const size_t HBW_L = (size_t)DES * H;
    const size_t HBB_L = (size_t)H;

    static int smem_set = 0;
    if (!smem_set) {
        cudaFuncSetAttribute(gemm_fp16, cudaFuncAttributeMaxDynamicSharedMemorySize, SMEM_BYTES);
        smem_set = 1;
    }

    embed_kernel<<<512, 256>>>(state, ew, eb);

    dim3 grid(4, 4, SPLITS);

    gemm_fp16<<<grid, 256, SMEM_BYTES>>>(0, cmd, hwW, hwb);
    reduce_bias_relu<<<512, 256>>>(cmd, hbW, hbb, out, 1);

    gemm_fp16<<<grid, 256, SMEM_BYTES>>>(1, cmd, hwW + HWW_L, hwb + HWB_L);
    reduce_bias_relu<<<512, 256>>>(cmd, hbW + HBW_L, hbb + HBB_L, out, 0);
}